// round 16
// baseline (speedup 1.0000x reference)
#include <cuda_runtime.h>
#include <cuda_fp16.h>
#include <math.h>
#include <stdint.h>

// ---------------------------------------------------------------------------
// Swin Transformer block: B=32, H=W=56, C=384, 12 heads, window 7, shift 3
// ---------------------------------------------------------------------------
#define Bb    32
#define Hh    56
#define Ww    56
#define Cc    384
#define HEADS 12
#define WS    7
#define SHIFT 3
#define HD    32
#define NTOK  49
#define NWIN  64
#define ROWS  100352
#define C3    1152
#define CH    1536
#define SCALE 0.17677669529663687f
#define LNEPS 1e-5f

// Scratch (static device memory — no allocation at runtime). Half precision.
__device__ __half g_win[(size_t)ROWS * Cc];
__device__ __half g_qkv[(size_t)ROWS * C3];
__device__ __half g_xa [(size_t)ROWS * Cc];
__device__ __half g_m1 [(size_t)ROWS * CH];
// transposed half weights ([N,K] layout): qkv | proj | fc1 | fc2
#define W_QKV 0
#define W_PROJ (Cc * C3)
#define W_FC1  (W_PROJ + Cc * Cc)
#define W_FC2  (W_FC1 + Cc * CH)
#define W_TOT  (W_FC2 + CH * Cc)
__device__ __half g_wh[W_TOT];

// ---------------------------------------------------------------------------
// One-time weight transpose ([K,N] fp32 -> [N,K] half)
// ---------------------------------------------------------------------------
__global__ void __launch_bounds__(256) wtrans_kernel(
    const float* __restrict__ src, __half* __restrict__ dst, int K, int N)
{
    __shared__ float t[32][33];
    int n0 = blockIdx.x * 32, k0 = blockIdx.y * 32;
    int tx = threadIdx.x, ty = threadIdx.y;   // 32 x 8
#pragma unroll
    for (int dy = 0; dy < 32; dy += 8)
        t[ty + dy][tx] = src[(size_t)(k0 + ty + dy) * N + n0 + tx];
    __syncthreads();
#pragma unroll
    for (int dy = 0; dy < 32; dy += 8)
        dst[(size_t)(n0 + ty + dy) * K + k0 + tx] = __float2half(t[tx][ty + dy]);
}

// ---------------------------------------------------------------------------
// LayerNorm (fused shift+window-partition gather when gather==1), half out
// ---------------------------------------------------------------------------
__global__ void __launch_bounds__(128) ln_kernel(
    const float* __restrict__ x, const float* __restrict__ g,
    const float* __restrict__ bt, __half* __restrict__ out, int gather)
{
    int r = blockIdx.x;
    int src = r;
    if (gather) {
        int n  = r % NTOK;
        int wl = (r / NTOK) % NWIN;
        int b  = r / (NTOK * NWIN);
        int wh = wl >> 3, ww = wl & 7;
        int i  = n / WS,  j  = n % WS;
        int oh = (wh * WS + i + SHIFT) % Hh;
        int ow = (ww * WS + j + SHIFT) % Ww;
        src = b * (Hh * Ww) + oh * Ww + ow;
    }
    const float* xp = x + (size_t)src * Cc;
    int tid = threadIdx.x;
    float v[3];
#pragma unroll
    for (int q = 0; q < 3; q++) v[q] = xp[tid + q * 128];
    float s  = v[0] + v[1] + v[2];
    float s2 = v[0]*v[0] + v[1]*v[1] + v[2]*v[2];
#pragma unroll
    for (int o = 16; o; o >>= 1) {
        s  += __shfl_xor_sync(0xffffffffu, s,  o);
        s2 += __shfl_xor_sync(0xffffffffu, s2, o);
    }
    __shared__ float sh[8];
    int wid = tid >> 5, lane = tid & 31;
    if (lane == 0) { sh[wid] = s; sh[wid + 4] = s2; }
    __syncthreads();
    float mu  = (sh[0] + sh[1] + sh[2] + sh[3]) * (1.0f / Cc);
    float var = (sh[4] + sh[5] + sh[6] + sh[7]) * (1.0f / Cc) - mu * mu;
    float rstd = rsqrtf(var + LNEPS);
    __half* op = out + (size_t)r * Cc;
#pragma unroll
    for (int q = 0; q < 3; q++) {
        int c = tid + q * 128;
        op[c] = __float2half((v[q] - mu) * rstd * g[c] + bt[c]);
    }
}

__device__ __forceinline__ int winrev_map(int m)
{
    int n  = m % NTOK;
    int wl = (m / NTOK) % NWIN;
    int b  = m / (NTOK * NWIN);
    int wh = wl >> 3, ww = wl & 7;
    int i  = n / WS,  j  = n % WS;
    int oh = (wh * WS + i + SHIFT) % Hh;
    int ow = (ww * WS + j + SHIFT) % Ww;
    return b * (Hh * Ww) + oh * Ww + ow;
}

__device__ __forceinline__ void ldsm4(uint32_t& r0, uint32_t& r1,
                                     uint32_t& r2, uint32_t& r3, uint32_t addr)
{
    asm volatile("ldmatrix.sync.aligned.m8n8.x4.shared.b16 {%0,%1,%2,%3}, [%4];"
                 : "=r"(r0), "=r"(r1), "=r"(r2), "=r"(r3) : "r"(addr));
}

__device__ __forceinline__ void cpa16(uint32_t dst, const void* src)
{
    asm volatile("cp.async.ca.shared.global [%0], [%1], 16;" :: "r"(dst), "l"(src));
}

// ---------------------------------------------------------------------------
// FP16 tensor-core GEMM (fp32 accumulate):
//   C[M,N] = A[M,K] @ Bt[N,K]^T + bias, fused epilogues.
// Block tile 128x128x64, 8 warps (64x32 each), mma.sync.m16n8k16.f16,
// 3-stage cp.async pipeline (prefetch distance 2 k-slabs = 128 K) +
// ldmatrix.x4 fragment loads. SMEM rows stride 72 halves (144 B):
// 8-row ldmatrix phases hit 16B-granules {0,16,..,112} mod 128 — conflict-free.
// EPI 0: half store. 1: winrev scatter + shortcut add (fp32).
// EPI 2: GELU, half store. 3: residual add (fp32).
// ---------------------------------------------------------------------------
#define BK 64
#define SROW 72                         // halves per row (64 + 8 pad)
#define STILE (128 * SROW)              // halves per matrix per stage
#define NSTG 3

template <int EPI>
__global__ void __launch_bounds__(256) mma_gemm(
    const __half* __restrict__ A, const __half* __restrict__ Bt,
    const float* __restrict__ bias, void* __restrict__ CoutV,
    int N, int K, const float* __restrict__ add_src)
{
    extern __shared__ __half smem[];
    __half* sA = smem;                  // [NSTG][STILE]
    __half* sB = smem + NSTG * STILE;   // [NSTG][STILE]

    const int tid  = threadIdx.x;
    const int lane = tid & 31;
    const int wid  = tid >> 5;          // 8 warps
    const int wm   = (wid & 1) * 64;
    const int wn   = (wid >> 1) * 32;
    const int m0   = blockIdx.y * 128;
    const int n0   = blockIdx.x * 128;

    // load mapping: thread -> row tid>>1, halves kc..kc+31 (four 16B chunks)
    const int r  = tid >> 1;
    const int kc = (tid & 1) * 32;
    const __half* gA = A  + (size_t)(m0 + r) * K + kc;
    const __half* gB = Bt + (size_t)(n0 + r) * K + kc;

    const uint32_t aDst0 = (uint32_t)__cvta_generic_to_shared(&sA[r * SROW + kc]);
    const uint32_t bDst0 = (uint32_t)__cvta_generic_to_shared(&sB[r * SROW + kc]);
    const uint32_t stageB = STILE * 2;  // bytes per stage

    const int KT = K / BK;

    auto issue = [&](int kt) {
        const int s = kt % NSTG;
        const __half* ga = gA + kt * BK;
        const __half* gb = gB + kt * BK;
#pragma unroll
        for (int c = 0; c < 4; c++) {
            cpa16(aDst0 + s * stageB + c * 16, ga + c * 8);
            cpa16(bDst0 + s * stageB + c * 16, gb + c * 8);
        }
        asm volatile("cp.async.commit_group;");
    };

    issue(0);
    if (KT > 1) issue(1);
    else        asm volatile("cp.async.commit_group;");

    float c[4][4][4] = {};

    // ldmatrix per-lane addresses (bytes).
    const int lm = lane >> 3, lr = lane & 7;
    const uint32_t sAb = (uint32_t)__cvta_generic_to_shared(&sA[0]);
    const uint32_t sBb = (uint32_t)__cvta_generic_to_shared(&sB[0]);
    const uint32_t aLane = ((wm + (lm & 1) * 8 + lr) * SROW + (lm >> 1) * 8) * 2;
    const uint32_t bLane = ((wn + (lm >> 1) * 8 + lr) * SROW + (lm & 1) * 8) * 2;

    for (int kt = 0; kt < KT; kt++) {
        if (kt + 1 < KT) asm volatile("cp.async.wait_group 1;");
        else             asm volatile("cp.async.wait_group 0;");
        __syncthreads();
        // stage (kt+2)%3 was fully consumed before the barrier above
        if (kt + 2 < KT) issue(kt + 2);

        const int s = kt % NSTG;
        const uint32_t aBase = sAb + s * stageB + aLane;
        const uint32_t bBase = sBb + s * stageB + bLane;
#pragma unroll
        for (int kk = 0; kk < 4; kk++) {            // four k16 steps
            uint32_t af[4][4], bf[4][2];
#pragma unroll
            for (int i = 0; i < 4; i++)
                ldsm4(af[i][0], af[i][1], af[i][2], af[i][3],
                      aBase + kk * 32 + i * 16 * SROW * 2);
#pragma unroll
            for (int jp = 0; jp < 2; jp++)
                ldsm4(bf[jp * 2][0], bf[jp * 2][1],
                      bf[jp * 2 + 1][0], bf[jp * 2 + 1][1],
                      bBase + kk * 32 + jp * 16 * SROW * 2);
#pragma unroll
            for (int i = 0; i < 4; i++)
#pragma unroll
                for (int j = 0; j < 4; j++)
                    asm volatile(
                        "mma.sync.aligned.m16n8k16.row.col.f32.f16.f16.f32 "
                        "{%0,%1,%2,%3}, {%4,%5,%6,%7}, {%8,%9}, {%0,%1,%2,%3};"
                        : "+f"(c[i][j][0]), "+f"(c[i][j][1]),
                          "+f"(c[i][j][2]), "+f"(c[i][j][3])
                        : "r"(af[i][0]), "r"(af[i][1]), "r"(af[i][2]), "r"(af[i][3]),
                          "r"(bf[j][0]), "r"(bf[j][1]));
        }
    }

    // epilogue
    __half* outH = (__half*)CoutV;
    float*  outF = (float*)CoutV;
#pragma unroll
    for (int i = 0; i < 4; i++) {
#pragma unroll
        for (int half_ = 0; half_ < 2; half_++) {
            int rr = m0 + wm + i * 16 + (lane >> 2) + half_ * 8;
            int dest = (EPI == 1) ? winrev_map(rr) : rr;
#pragma unroll
            for (int j = 0; j < 4; j++) {
                int cn = n0 + wn + j * 8 + (lane & 3) * 2;
                float v0 = c[i][j][half_ * 2 + 0] + bias[cn];
                float v1 = c[i][j][half_ * 2 + 1] + bias[cn + 1];
                if (EPI == 0) {
                    *(__half2*)&outH[(size_t)rr * N + cn] = __floats2half2_rn(v0, v1);
                } else if (EPI == 1) {
                    size_t idx = (size_t)dest * Cc + cn;
                    *(float2*)&outF[idx] =
                        make_float2(add_src[idx] + v0, add_src[idx + 1] + v1);
                } else if (EPI == 2) {
                    v0 = 0.5f * v0 * (1.0f + erff(v0 * 0.70710678118654752f));
                    v1 = 0.5f * v1 * (1.0f + erff(v1 * 0.70710678118654752f));
                    *(__half2*)&outH[(size_t)rr * N + cn] = __floats2half2_rn(v0, v1);
                } else { // EPI == 3
                    size_t idx = (size_t)rr * N + cn;
                    *(float2*)&outF[idx] =
                        make_float2(add_src[idx] + v0, add_src[idx + 1] + v1);
                }
            }
        }
    }
}

// ---------------------------------------------------------------------------
// Windowed attention (R13 version): one block per (window, head). N=49, HD=32.
// half in (qkv), half out (xa); fp32 math inside.
// ---------------------------------------------------------------------------
__global__ void __launch_bounds__(64) attn_kernel(
    const __half* __restrict__ qkv, const float* __restrict__ rpb,
    __half* __restrict__ xa)
{
    int head = blockIdx.x;
    int bwin = blockIdx.y;
    __shared__ float qs[NTOK * HD], ks[NTOK * HD], vs[NTOK * HD];
    int tid = threadIdx.x;

    const __half* base = qkv + (size_t)bwin * NTOK * C3 + head * HD;
    for (int idx = tid; idx < NTOK * HD; idx += 64) {
        int n = idx >> 5, d = idx & 31;
        size_t off = (size_t)n * C3 + d;
        qs[idx] = __half2float(base[off]);
        ks[idx] = __half2float(base[off + Cc]);
        vs[idx] = __half2float(base[off + 2 * Cc]);
    }
    __syncthreads();

    if (tid < NTOK) {
        int n = tid;
        float q[HD];
#pragma unroll
        for (int d = 0; d < HD; d++) q[d] = qs[n * HD + d] * SCALE;

        int in_ = n / WS, jn = n % WS;
        int wl = bwin & (NWIN - 1);
        int wh = wl >> 3, ww = wl & 7;
        int hs_n = wh * WS + in_, ws_n = ww * WS + jn;
        int lab_n = (hs_n < Hh - WS ? 0 : (hs_n < Hh - SHIFT ? 1 : 2)) * 3
                  + (ws_n < Ww - WS ? 0 : (ws_n < Ww - SHIFT ? 1 : 2));

        float s[NTOK];
        float mx = -1e30f;
        for (int m = 0; m < NTOK; m++) {
            float dot = 0.0f;
#pragma unroll
            for (int d = 0; d < HD; d++) dot += q[d] * ks[m * HD + d];
            int im = m / WS, jm = m % WS;
            int hs_m = wh * WS + im, ws_m = ww * WS + jm;
            int lab_m = (hs_m < Hh - WS ? 0 : (hs_m < Hh - SHIFT ? 1 : 2)) * 3
                      + (ws_m < Ww - WS ? 0 : (ws_m < Ww - SHIFT ? 1 : 2));
            int rel = (in_ - im + WS - 1) * (2 * WS - 1) + (jn - jm + WS - 1);
            dot += rpb[rel * HEADS + head];
            if (lab_m != lab_n) dot -= 100.0f;
            s[m] = dot;
            mx = fmaxf(mx, dot);
        }
        float sum = 0.0f;
        for (int m = 0; m < NTOK; m++) { s[m] = __expf(s[m] - mx); sum += s[m]; }
        float inv = 1.0f / sum;

        float o[HD];
#pragma unroll
        for (int d = 0; d < HD; d++) o[d] = 0.0f;
        for (int m = 0; m < NTOK; m++) {
            float p = s[m] * inv;
#pragma unroll
            for (int d = 0; d < HD; d++) o[d] += p * vs[m * HD + d];
        }
        __half* dst = xa + ((size_t)bwin * NTOK + n) * Cc + head * HD;
#pragma unroll
        for (int d = 0; d < HD; d++) dst[d] = __float2half(o[d]);
    }
}

// ---------------------------------------------------------------------------
// Launch
// ---------------------------------------------------------------------------
extern "C" void kernel_launch(void* const* d_in, const int* in_sizes, int n_in,
                              void* d_out, int out_size)
{
    const float* x      = (const float*)d_in[0];
    const float* ln1_g  = (const float*)d_in[1];
    const float* ln1_b  = (const float*)d_in[2];
    const float* qkv_w  = (const float*)d_in[3];
    const float* qkv_b  = (const float*)d_in[4];
    const float* rpb    = (const float*)d_in[5];
    const float* proj_w = (const float*)d_in[6];
    const float* proj_b = (const float*)d_in[7];
    const float* ln2_g  = (const float*)d_in[8];
    const float* ln2_b  = (const float*)d_in[9];
    const float* fc1_w  = (const float*)d_in[10];
    const float* fc1_b  = (const float*)d_in[11];
    const float* fc2_w  = (const float*)d_in[12];
    const float* fc2_b  = (const float*)d_in[13];
    float* out = (float*)d_out;

    __half *p_win, *p_qkv, *p_xa, *p_m1, *p_wh;
    cudaGetSymbolAddress((void**)&p_win, g_win);
    cudaGetSymbolAddress((void**)&p_qkv, g_qkv);
    cudaGetSymbolAddress((void**)&p_xa,  g_xa);
    cudaGetSymbolAddress((void**)&p_m1,  g_m1);
    cudaGetSymbolAddress((void**)&p_wh,  g_wh);

    const int smem_bytes = NSTG * STILE * 2 * 2;   // 110592 B
    cudaFuncSetAttribute(mma_gemm<0>, cudaFuncAttributeMaxDynamicSharedMemorySize, smem_bytes);
    cudaFuncSetAttribute(mma_gemm<1>, cudaFuncAttributeMaxDynamicSharedMemorySize, smem_bytes);
    cudaFuncSetAttribute(mma_gemm<2>, cudaFuncAttributeMaxDynamicSharedMemorySize, smem_bytes);
    cudaFuncSetAttribute(mma_gemm<3>, cudaFuncAttributeMaxDynamicSharedMemorySize, smem_bytes);

    dim3 tb(32, 8);
    // 0. one-time weight transpose+convert ([K,N] fp32 -> [N,K] half)
    wtrans_kernel<<<dim3(C3 / 32, Cc / 32), tb>>>(qkv_w,  p_wh + W_QKV, Cc, C3);
    wtrans_kernel<<<dim3(Cc / 32, Cc / 32), tb>>>(proj_w, p_wh + W_PROJ, Cc, Cc);
    wtrans_kernel<<<dim3(CH / 32, Cc / 32), tb>>>(fc1_w,  p_wh + W_FC1, Cc, CH);
    wtrans_kernel<<<dim3(Cc / 32, CH / 32), tb>>>(fc2_w,  p_wh + W_FC2, CH, Cc);

    // 1. LN1 + shift + window partition (half out)
    ln_kernel<<<ROWS, 128>>>(x, ln1_g, ln1_b, p_win, 1);

    // 2. qkv GEMM: [ROWS,384] @ [384,1152] -> half  (K/BK = 6 slabs)
    mma_gemm<0><<<dim3(C3 / 128, ROWS / 128), 256, smem_bytes>>>(
        p_win, p_wh + W_QKV, qkv_b, p_qkv, C3, Cc, nullptr);

    // 3. windowed attention (half -> half)
    attn_kernel<<<dim3(HEADS, ROWS / NTOK), 64>>>(p_qkv, rpb, p_xa);

    // 4. proj GEMM + window reverse + unshift + shortcut add -> d_out (fp32)
    mma_gemm<1><<<dim3(Cc / 128, ROWS / 128), 256, smem_bytes>>>(
        p_xa, p_wh + W_PROJ, proj_b, out, Cc, Cc, x);

    // 5. LN2 on d_out (half out)
    ln_kernel<<<ROWS, 128>>>(out, ln2_g, ln2_b, p_win, 0);

    // 6. fc1 GEMM + GELU: [ROWS,384] @ [384,1536] -> half
    mma_gemm<2><<<dim3(CH / 128, ROWS / 128), 256, smem_bytes>>>(
        p_win, p_wh + W_FC1, fc1_b, p_m1, CH, Cc, nullptr);

    // 7. fc2 GEMM + residual add: [ROWS,1536] @ [1536,384] -> d_out (fp32)
    mma_gemm<3><<<dim3(Cc / 128, ROWS / 128), 256, smem_bytes>>>(
        p_m1, p_wh + W_FC2, fc2_b, out, Cc, CH, out);
}

// round 17
// speedup vs baseline: 1.2850x; 1.2850x over previous
#include <cuda_runtime.h>
#include <cuda_fp16.h>
#include <math.h>
#include <stdint.h>

// ---------------------------------------------------------------------------
// Swin Transformer block: B=32, H=W=56, C=384, 12 heads, window 7, shift 3
// ---------------------------------------------------------------------------
#define Bb    32
#define Hh    56
#define Ww    56
#define Cc    384
#define HEADS 12
#define WS    7
#define SHIFT 3
#define HD    32
#define NTOK  49
#define NWIN  64
#define ROWS  100352
#define C3    1152
#define CH    1536
#define SCALE 0.17677669529663687f
#define LNEPS 1e-5f

// Scratch (static device memory — no allocation at runtime). Half precision.
__device__ __half g_win[(size_t)ROWS * Cc];
__device__ __half g_qkv[(size_t)ROWS * C3];
__device__ __half g_xa [(size_t)ROWS * Cc];
__device__ __half g_m1 [(size_t)ROWS * CH];
// transposed half weights ([N,K] layout): qkv | proj | fc1 | fc2
#define W_QKV 0
#define W_PROJ (Cc * C3)
#define W_FC1  (W_PROJ + Cc * Cc)
#define W_FC2  (W_FC1 + Cc * CH)
#define W_TOT  (W_FC2 + CH * Cc)
__device__ __half g_wh[W_TOT];

// ---------------------------------------------------------------------------
// One-time weight transpose ([K,N] fp32 -> [N,K] half)
// ---------------------------------------------------------------------------
__global__ void __launch_bounds__(256) wtrans_kernel(
    const float* __restrict__ src, __half* __restrict__ dst, int K, int N)
{
    __shared__ float t[32][33];
    int n0 = blockIdx.x * 32, k0 = blockIdx.y * 32;
    int tx = threadIdx.x, ty = threadIdx.y;   // 32 x 8
#pragma unroll
    for (int dy = 0; dy < 32; dy += 8)
        t[ty + dy][tx] = src[(size_t)(k0 + ty + dy) * N + n0 + tx];
    __syncthreads();
#pragma unroll
    for (int dy = 0; dy < 32; dy += 8)
        dst[(size_t)(n0 + ty + dy) * K + k0 + tx] = __float2half(t[tx][ty + dy]);
}

// ---------------------------------------------------------------------------
// LayerNorm v2: one WARP per row (no smem, no block barriers).
// 256 threads = 8 rows per block. Each lane holds 12 values (3 x float4).
// gather==1 fuses shift + window-partition source mapping (LN1).
// ---------------------------------------------------------------------------
__global__ void __launch_bounds__(256) ln_kernel(
    const float* __restrict__ x, const float* __restrict__ g,
    const float* __restrict__ bt, __half* __restrict__ out, int gather)
{
    const int warp = threadIdx.x >> 5;
    const int lane = threadIdx.x & 31;
    const int r = blockIdx.x * 8 + warp;

    int src = r;
    if (gather) {
        int n  = r % NTOK;
        int wl = (r / NTOK) % NWIN;
        int b  = r / (NTOK * NWIN);
        int wh = wl >> 3, ww = wl & 7;
        int i  = n / WS,  j  = n % WS;
        int oh = (wh * WS + i + SHIFT) % Hh;
        int ow = (ww * WS + j + SHIFT) % Ww;
        src = b * (Hh * Ww) + oh * Ww + ow;
    }

    const float4* xp = (const float4*)(x + (size_t)src * Cc);
    float4 v[3];
#pragma unroll
    for (int q = 0; q < 3; q++) v[q] = xp[q * 32 + lane];

    float s = 0.0f, s2 = 0.0f;
#pragma unroll
    for (int q = 0; q < 3; q++) {
        s  += v[q].x + v[q].y + v[q].z + v[q].w;
        s2 += v[q].x * v[q].x + v[q].y * v[q].y
            + v[q].z * v[q].z + v[q].w * v[q].w;
    }
#pragma unroll
    for (int o = 16; o; o >>= 1) {
        s  += __shfl_xor_sync(0xffffffffu, s,  o);
        s2 += __shfl_xor_sync(0xffffffffu, s2, o);
    }
    const float mu   = s * (1.0f / Cc);
    const float var  = s2 * (1.0f / Cc) - mu * mu;
    const float rstd = rsqrtf(var + LNEPS);

    const float4* g4  = (const float4*)g;
    const float4* bt4 = (const float4*)bt;
    uint2* op = (uint2*)(out + (size_t)r * Cc);
#pragma unroll
    for (int q = 0; q < 3; q++) {
        const int c4 = q * 32 + lane;
        float4 gg = g4[c4], bb = bt4[c4];
        float o0 = (v[q].x - mu) * rstd * gg.x + bb.x;
        float o1 = (v[q].y - mu) * rstd * gg.y + bb.y;
        float o2 = (v[q].z - mu) * rstd * gg.z + bb.z;
        float o3 = (v[q].w - mu) * rstd * gg.w + bb.w;
        __half2 h0 = __floats2half2_rn(o0, o1);
        __half2 h1 = __floats2half2_rn(o2, o3);
        uint2 u;
        u.x = *(uint32_t*)&h0;
        u.y = *(uint32_t*)&h1;
        op[c4] = u;
    }
}

__device__ __forceinline__ int winrev_map(int m)
{
    int n  = m % NTOK;
    int wl = (m / NTOK) % NWIN;
    int b  = m / (NTOK * NWIN);
    int wh = wl >> 3, ww = wl & 7;
    int i  = n / WS,  j  = n % WS;
    int oh = (wh * WS + i + SHIFT) % Hh;
    int ow = (ww * WS + j + SHIFT) % Ww;
    return b * (Hh * Ww) + oh * Ww + ow;
}

__device__ __forceinline__ void ldsm4(uint32_t& r0, uint32_t& r1,
                                     uint32_t& r2, uint32_t& r3, uint32_t addr)
{
    asm volatile("ldmatrix.sync.aligned.m8n8.x4.shared.b16 {%0,%1,%2,%3}, [%4];"
                 : "=r"(r0), "=r"(r1), "=r"(r2), "=r"(r3) : "r"(addr));
}

__device__ __forceinline__ void cpa16(uint32_t dst, const void* src)
{
    asm volatile("cp.async.ca.shared.global [%0], [%1], 16;" :: "r"(dst), "l"(src));
}

// ---------------------------------------------------------------------------
// FP16 tensor-core GEMM (fp32 accumulate) — R13 configuration (best).
// Block tile 128x128x32, 8 warps (64x32 each), mma.sync.m16n8k16.f16,
// 3-stage cp.async pipeline + ldmatrix.x4 fragment loads.
// SMEM rows stride 40 halves (80 B): conflict-free ldmatrix.
// EPI 0: half store. 1: winrev scatter + shortcut add (fp32).
// EPI 2: GELU, half store. 3: residual add (fp32).
// ---------------------------------------------------------------------------
#define BK 32
#define SROW 40                         // halves per row (32 + 8 pad)
#define STILE (128 * SROW)              // halves per matrix per stage
#define NSTG 3

template <int EPI>
__global__ void __launch_bounds__(256) mma_gemm(
    const __half* __restrict__ A, const __half* __restrict__ Bt,
    const float* __restrict__ bias, void* __restrict__ CoutV,
    int N, int K, const float* __restrict__ add_src)
{
    extern __shared__ __half smem[];
    __half* sA = smem;                  // [NSTG][STILE]
    __half* sB = smem + NSTG * STILE;   // [NSTG][STILE]

    const int tid  = threadIdx.x;
    const int lane = tid & 31;
    const int wid  = tid >> 5;          // 8 warps
    const int wm   = (wid & 1) * 64;
    const int wn   = (wid >> 1) * 32;
    const int m0   = blockIdx.y * 128;
    const int n0   = blockIdx.x * 128;

    // load mapping: thread -> row tid>>1, halves kc..kc+15 (two 16B chunks)
    const int r  = tid >> 1;
    const int kc = (tid & 1) * 16;
    const __half* gA = A  + (size_t)(m0 + r) * K + kc;
    const __half* gB = Bt + (size_t)(n0 + r) * K + kc;

    const uint32_t aDst0 = (uint32_t)__cvta_generic_to_shared(&sA[r * SROW + kc]);
    const uint32_t bDst0 = (uint32_t)__cvta_generic_to_shared(&sB[r * SROW + kc]);
    const uint32_t stageB = STILE * 2;  // bytes per stage

    const int KT = K / BK;

    auto issue = [&](int kt) {
        const int s = kt % NSTG;
        const __half* ga = gA + kt * BK;
        const __half* gb = gB + kt * BK;
        cpa16(aDst0 + s * stageB,      ga);
        cpa16(aDst0 + s * stageB + 16, ga + 8);
        cpa16(bDst0 + s * stageB,      gb);
        cpa16(bDst0 + s * stageB + 16, gb + 8);
        asm volatile("cp.async.commit_group;");
    };

    issue(0);
    issue(1);

    float c[4][4][4] = {};

    // ldmatrix per-lane addresses (bytes).
    const int lm = lane >> 3, lr = lane & 7;
    const uint32_t sAb = (uint32_t)__cvta_generic_to_shared(&sA[0]);
    const uint32_t sBb = (uint32_t)__cvta_generic_to_shared(&sB[0]);
    const uint32_t aLane = ((wm + (lm & 1) * 8 + lr) * SROW + (lm >> 1) * 8) * 2;
    const uint32_t bLane = ((wn + (lm >> 1) * 8 + lr) * SROW + (lm & 1) * 8) * 2;

    for (int kt = 0; kt < KT; kt++) {
        if (kt + 1 < KT) asm volatile("cp.async.wait_group 1;");
        else             asm volatile("cp.async.wait_group 0;");
        __syncthreads();
        // stage (kt+2)%3 was fully consumed before the barrier above
        if (kt + 2 < KT) issue(kt + 2);

        const int s = kt % NSTG;
        const uint32_t aBase = sAb + s * stageB + aLane;
        const uint32_t bBase = sBb + s * stageB + bLane;
#pragma unroll
        for (int kk = 0; kk < 2; kk++) {            // two k16 steps
            uint32_t af[4][4], bf[4][2];
#pragma unroll
            for (int i = 0; i < 4; i++)
                ldsm4(af[i][0], af[i][1], af[i][2], af[i][3],
                      aBase + kk * 32 + i * 16 * SROW * 2);
#pragma unroll
            for (int jp = 0; jp < 2; jp++)
                ldsm4(bf[jp * 2][0], bf[jp * 2][1],
                      bf[jp * 2 + 1][0], bf[jp * 2 + 1][1],
                      bBase + kk * 32 + jp * 16 * SROW * 2);
#pragma unroll
            for (int i = 0; i < 4; i++)
#pragma unroll
                for (int j = 0; j < 4; j++)
                    asm volatile(
                        "mma.sync.aligned.m16n8k16.row.col.f32.f16.f16.f32 "
                        "{%0,%1,%2,%3}, {%4,%5,%6,%7}, {%8,%9}, {%0,%1,%2,%3};"
                        : "+f"(c[i][j][0]), "+f"(c[i][j][1]),
                          "+f"(c[i][j][2]), "+f"(c[i][j][3])
                        : "r"(af[i][0]), "r"(af[i][1]), "r"(af[i][2]), "r"(af[i][3]),
                          "r"(bf[j][0]), "r"(bf[j][1]));
        }
    }

    // epilogue
    __half* outH = (__half*)CoutV;
    float*  outF = (float*)CoutV;
#pragma unroll
    for (int i = 0; i < 4; i++) {
#pragma unroll
        for (int half_ = 0; half_ < 2; half_++) {
            int rr = m0 + wm + i * 16 + (lane >> 2) + half_ * 8;
            int dest = (EPI == 1) ? winrev_map(rr) : rr;
#pragma unroll
            for (int j = 0; j < 4; j++) {
                int cn = n0 + wn + j * 8 + (lane & 3) * 2;
                float v0 = c[i][j][half_ * 2 + 0] + bias[cn];
                float v1 = c[i][j][half_ * 2 + 1] + bias[cn + 1];
                if (EPI == 0) {
                    *(__half2*)&outH[(size_t)rr * N + cn] = __floats2half2_rn(v0, v1);
                } else if (EPI == 1) {
                    size_t idx = (size_t)dest * Cc + cn;
                    *(float2*)&outF[idx] =
                        make_float2(add_src[idx] + v0, add_src[idx + 1] + v1);
                } else if (EPI == 2) {
                    v0 = 0.5f * v0 * (1.0f + erff(v0 * 0.70710678118654752f));
                    v1 = 0.5f * v1 * (1.0f + erff(v1 * 0.70710678118654752f));
                    *(__half2*)&outH[(size_t)rr * N + cn] = __floats2half2_rn(v0, v1);
                } else { // EPI == 3
                    size_t idx = (size_t)rr * N + cn;
                    *(float2*)&outF[idx] =
                        make_float2(add_src[idx] + v0, add_src[idx + 1] + v1);
                }
            }
        }
    }
}

// ---------------------------------------------------------------------------
// Windowed attention (R13 version): one block per (window, head). N=49, HD=32.
// half in (qkv), half out (xa); fp32 math inside.
// ---------------------------------------------------------------------------
__global__ void __launch_bounds__(64) attn_kernel(
    const __half* __restrict__ qkv, const float* __restrict__ rpb,
    __half* __restrict__ xa)
{
    int head = blockIdx.x;
    int bwin = blockIdx.y;
    __shared__ float qs[NTOK * HD], ks[NTOK * HD], vs[NTOK * HD];
    int tid = threadIdx.x;

    const __half* base = qkv + (size_t)bwin * NTOK * C3 + head * HD;
    for (int idx = tid; idx < NTOK * HD; idx += 64) {
        int n = idx >> 5, d = idx & 31;
        size_t off = (size_t)n * C3 + d;
        qs[idx] = __half2float(base[off]);
        ks[idx] = __half2float(base[off + Cc]);
        vs[idx] = __half2float(base[off + 2 * Cc]);
    }
    __syncthreads();

    if (tid < NTOK) {
        int n = tid;
        float q[HD];
#pragma unroll
        for (int d = 0; d < HD; d++) q[d] = qs[n * HD + d] * SCALE;

        int in_ = n / WS, jn = n % WS;
        int wl = bwin & (NWIN - 1);
        int wh = wl >> 3, ww = wl & 7;
        int hs_n = wh * WS + in_, ws_n = ww * WS + jn;
        int lab_n = (hs_n < Hh - WS ? 0 : (hs_n < Hh - SHIFT ? 1 : 2)) * 3
                  + (ws_n < Ww - WS ? 0 : (ws_n < Ww - SHIFT ? 1 : 2));

        float s[NTOK];
        float mx = -1e30f;
        for (int m = 0; m < NTOK; m++) {
            float dot = 0.0f;
#pragma unroll
            for (int d = 0; d < HD; d++) dot += q[d] * ks[m * HD + d];
            int im = m / WS, jm = m % WS;
            int hs_m = wh * WS + im, ws_m = ww * WS + jm;
            int lab_m = (hs_m < Hh - WS ? 0 : (hs_m < Hh - SHIFT ? 1 : 2)) * 3
                      + (ws_m < Ww - WS ? 0 : (ws_m < Ww - SHIFT ? 1 : 2));
            int rel = (in_ - im + WS - 1) * (2 * WS - 1) + (jn - jm + WS - 1);
            dot += rpb[rel * HEADS + head];
            if (lab_m != lab_n) dot -= 100.0f;
            s[m] = dot;
            mx = fmaxf(mx, dot);
        }
        float sum = 0.0f;
        for (int m = 0; m < NTOK; m++) { s[m] = __expf(s[m] - mx); sum += s[m]; }
        float inv = 1.0f / sum;

        float o[HD];
#pragma unroll
        for (int d = 0; d < HD; d++) o[d] = 0.0f;
        for (int m = 0; m < NTOK; m++) {
            float p = s[m] * inv;
#pragma unroll
            for (int d = 0; d < HD; d++) o[d] += p * vs[m * HD + d];
        }
        __half* dst = xa + ((size_t)bwin * NTOK + n) * Cc + head * HD;
#pragma unroll
        for (int d = 0; d < HD; d++) dst[d] = __float2half(o[d]);
    }
}

// ---------------------------------------------------------------------------
// Launch
// ---------------------------------------------------------------------------
extern "C" void kernel_launch(void* const* d_in, const int* in_sizes, int n_in,
                              void* d_out, int out_size)
{
    const float* x      = (const float*)d_in[0];
    const float* ln1_g  = (const float*)d_in[1];
    const float* ln1_b  = (const float*)d_in[2];
    const float* qkv_w  = (const float*)d_in[3];
    const float* qkv_b  = (const float*)d_in[4];
    const float* rpb    = (const float*)d_in[5];
    const float* proj_w = (const float*)d_in[6];
    const float* proj_b = (const float*)d_in[7];
    const float* ln2_g  = (const float*)d_in[8];
    const float* ln2_b  = (const float*)d_in[9];
    const float* fc1_w  = (const float*)d_in[10];
    const float* fc1_b  = (const float*)d_in[11];
    const float* fc2_w  = (const float*)d_in[12];
    const float* fc2_b  = (const float*)d_in[13];
    float* out = (float*)d_out;

    __half *p_win, *p_qkv, *p_xa, *p_m1, *p_wh;
    cudaGetSymbolAddress((void**)&p_win, g_win);
    cudaGetSymbolAddress((void**)&p_qkv, g_qkv);
    cudaGetSymbolAddress((void**)&p_xa,  g_xa);
    cudaGetSymbolAddress((void**)&p_m1,  g_m1);
    cudaGetSymbolAddress((void**)&p_wh,  g_wh);

    const int smem_bytes = NSTG * STILE * 2 * 2;   // 61440 B
    cudaFuncSetAttribute(mma_gemm<0>, cudaFuncAttributeMaxDynamicSharedMemorySize, smem_bytes);
    cudaFuncSetAttribute(mma_gemm<1>, cudaFuncAttributeMaxDynamicSharedMemorySize, smem_bytes);
    cudaFuncSetAttribute(mma_gemm<2>, cudaFuncAttributeMaxDynamicSharedMemorySize, smem_bytes);
    cudaFuncSetAttribute(mma_gemm<3>, cudaFuncAttributeMaxDynamicSharedMemorySize, smem_bytes);

    dim3 tb(32, 8);
    // 0. one-time weight transpose+convert ([K,N] fp32 -> [N,K] half)
    wtrans_kernel<<<dim3(C3 / 32, Cc / 32), tb>>>(qkv_w,  p_wh + W_QKV, Cc, C3);
    wtrans_kernel<<<dim3(Cc / 32, Cc / 32), tb>>>(proj_w, p_wh + W_PROJ, Cc, Cc);
    wtrans_kernel<<<dim3(CH / 32, Cc / 32), tb>>>(fc1_w,  p_wh + W_FC1, Cc, CH);
    wtrans_kernel<<<dim3(Cc / 32, CH / 32), tb>>>(fc2_w,  p_wh + W_FC2, CH, Cc);

    // 1. LN1 + shift + window partition (half out), warp-per-row
    ln_kernel<<<ROWS / 8, 256>>>(x, ln1_g, ln1_b, p_win, 1);

    // 2. qkv GEMM: [ROWS,384] @ [384,1152] -> half
    mma_gemm<0><<<dim3(C3 / 128, ROWS / 128), 256, smem_bytes>>>(
        p_win, p_wh + W_QKV, qkv_b, p_qkv, C3, Cc, nullptr);

    // 3. windowed attention (half -> half)
    attn_kernel<<<dim3(HEADS, ROWS / NTOK), 64>>>(p_qkv, rpb, p_xa);

    // 4. proj GEMM + window reverse + unshift + shortcut add -> d_out (fp32)
    mma_gemm<1><<<dim3(Cc / 128, ROWS / 128), 256, smem_bytes>>>(
        p_xa, p_wh + W_PROJ, proj_b, out, Cc, Cc, x);

    // 5. LN2 on d_out (half out), warp-per-row
    ln_kernel<<<ROWS / 8, 256>>>(out, ln2_g, ln2_b, p_win, 0);

    // 6. fc1 GEMM + GELU: [ROWS,384] @ [384,1536] -> half
    mma_gemm<2><<<dim3(CH / 128, ROWS / 128), 256, smem_bytes>>>(
        p_win, p_wh + W_FC1, fc1_b, p_m1, CH, Cc, nullptr);

    // 7. fc2 GEMM + residual add: [ROWS,1536] @ [1536,384] -> d_out (fp32)
    mma_gemm<3><<<dim3(Cc / 128, ROWS / 128), 256, smem_bytes>>>(
        p_m1, p_wh + W_FC2, fc2_b, out, Cc, CH, out);
}